// round 13
// baseline (speedup 1.0000x reference)
#include <cuda_runtime.h>
#include <cuda_fp16.h>
#include <cstdint>

#define BB    16
#define CIN   512
#define COUT  512
#define RES   64
#define WDIM  512
#define PADW  66
#define NPIX  (PADW * PADW)

// ---------------------------------------------------------------------------
// device scratch (static globals — no allocations allowed)
// ---------------------------------------------------------------------------
__device__ float g_proj[BB * 3 * CIN];
__device__ float g_styles[BB * CIN];
__device__ float g_dcoefs[BB * COUT];
__device__ __align__(1024) __half g_a[9ull * COUT * CIN];          // [tap][cout][cin]
__device__ __align__(1024) __half g_x[(size_t)BB * NPIX * CIN];    // [b][pixel][cin]

// ---------------------------------------------------------------------------
// PTX helpers (baseline compute_103-safe)
// ---------------------------------------------------------------------------
__device__ __forceinline__ uint32_t smem_u32(const void* p) {
    uint32_t a;
    asm("{ .reg .u64 t; cvta.to.shared.u64 t, %1; cvt.u32.u64 %0, t; }" : "=r"(a) : "l"(p));
    return a;
}
__device__ __forceinline__ void cpa16(uint32_t dst, const void* src) {
    asm volatile("cp.async.cg.shared.global [%0], [%1], 16;" :: "r"(dst), "l"(src));
}
#define CP_COMMIT()  asm volatile("cp.async.commit_group;" ::: "memory")
#define CP_WAIT1()   asm volatile("cp.async.wait_group 1;" ::: "memory")
#define CP_WAIT0()   asm volatile("cp.async.wait_group 0;" ::: "memory")

__device__ __forceinline__ void ldsm4(uint32_t* r, uint32_t a) {
    asm volatile("ldmatrix.sync.aligned.m8n8.x4.shared.b16 {%0,%1,%2,%3}, [%4];"
        : "=r"(r[0]), "=r"(r[1]), "=r"(r[2]), "=r"(r[3]) : "r"(a));
}
__device__ __forceinline__ void mma_f16(float* c, const uint32_t* a, const uint32_t* b) {
    asm volatile("mma.sync.aligned.m16n8k16.row.col.f32.f16.f16.f32 "
        "{%0,%1,%2,%3}, {%4,%5,%6,%7}, {%8,%9}, {%0,%1,%2,%3};"
        : "+f"(c[0]), "+f"(c[1]), "+f"(c[2]), "+f"(c[3])
        : "r"(a[0]), "r"(a[1]), "r"(a[2]), "r"(a[3]), "r"(b[0]), "r"(b[1]));
}
__device__ __forceinline__ uint32_t sw128(uint32_t off) {
    return off ^ ((off >> 3) & 0x70);
}

// ---------------------------------------------------------------------------
// prep kernel 1: coalesced styles GEMV (warp per affine_w row)
// ---------------------------------------------------------------------------
__global__ void k_styles(const float* __restrict__ w,
                         const float* __restrict__ affine_w,
                         const float* __restrict__ affine_b) {
    __shared__ float sw[BB][WDIM];
    const int tid = threadIdx.x;
    for (int i = tid; i < BB * WDIM; i += 256)
        ((float*)sw)[i] = w[i];
    __syncthreads();

    const int wid = tid >> 5, lid = tid & 31;
    const int j = blockIdx.x * 8 + wid;
    const float* __restrict__ row = affine_w + (size_t)j * WDIM;

    float acc[BB];
#pragma unroll
    for (int b = 0; b < BB; b++) acc[b] = 0.f;
#pragma unroll 4
    for (int k = lid; k < WDIM; k += 32) {
        const float rv = row[k];
#pragma unroll
        for (int b = 0; b < BB; b++) acc[b] += rv * sw[b][k];
    }
#pragma unroll
    for (int b = 0; b < BB; b++)
#pragma unroll
        for (int off = 16; off > 0; off >>= 1)
            acc[b] += __shfl_xor_sync(0xFFFFFFFFu, acc[b], off);

    if (lid < BB) {
        const float gain = 1.0f / sqrtf((float)WDIM);
        g_proj[lid * 3 * CIN + j] = acc[lid] * gain + affine_b[j];
    }
}

// ---------------------------------------------------------------------------
// prep kernel 2 (fused): styles = m1*m2+m3, pack weights fp16, wsq, dcoefs
// ---------------------------------------------------------------------------
__global__ void k_prep(const float* __restrict__ weight) {
    const int co = blockIdx.x, ci = threadIdx.x;

    float st[BB];
#pragma unroll
    for (int b = 0; b < BB; b++) {
        const float m1 = g_proj[b * 3 * CIN + 0 * CIN + ci];
        const float m2 = g_proj[b * 3 * CIN + 1 * CIN + ci];
        const float m3 = g_proj[b * 3 * CIN + 2 * CIN + ci];
        st[b] = m1 * m2 + m3;
    }
    if (co == 0) {
#pragma unroll
        for (int b = 0; b < BB; b++) g_styles[b * CIN + ci] = st[b];
    }

    const float* __restrict__ wp = weight + ((size_t)co * CIN + ci) * 9;
    float s = 0.f;
#pragma unroll
    for (int t = 0; t < 9; t++) {
        const float v = wp[t];
        s += v * v;
        g_a[((size_t)t * COUT + co) * CIN + ci] = __float2half(v);
    }
    float p[BB];
#pragma unroll
    for (int b = 0; b < BB; b++) p[b] = st[b] * st[b] * s;
#pragma unroll
    for (int b = 0; b < BB; b++)
#pragma unroll
        for (int off = 16; off > 0; off >>= 1)
            p[b] += __shfl_xor_sync(0xFFFFFFFFu, p[b], off);
    __shared__ float red[BB][17];
    const int wrp = ci >> 5, lane = ci & 31;
    if (lane == 0)
#pragma unroll
        for (int b = 0; b < BB; b++) red[b][wrp] = p[b];
    __syncthreads();
    if (ci < BB) {
        float acc = 0.f;
#pragma unroll
        for (int k = 0; k < 16; k++) acc += red[ci][k];
        g_dcoefs[ci * COUT + co] = rsqrtf(acc + 1e-8f);
    }
}

// ---------------------------------------------------------------------------
// prep kernel 3: pack modulated input (fp16) + padding ring (fused)
// ---------------------------------------------------------------------------
__global__ void k_pack_x(const float* __restrict__ x) {
    const int b = blockIdx.z, hp = blockIdx.y, cin0 = blockIdx.x * 32;
    const int t = threadIdx.x;
    const __half zz = __float2half(0.f);

    if (hp == 0 || hp == 65) {
        for (int idx = t; idx < 66 * 32; idx += 256) {
            const int pw = idx >> 5, c = idx & 31;
            g_x[((size_t)b * NPIX + hp * PADW + pw) * CIN + cin0 + c] = zz;
        }
        return;
    }
    const int h = hp - 1;
    __shared__ float tile[32][65];
    {
        const int w = t & 63, i0 = t >> 6;
#pragma unroll
        for (int j = 0; j < 8; j++) {
            const int ci = i0 * 8 + j;
            tile[ci][w] = x[(((size_t)b * CIN + cin0 + ci) * RES + h) * RES + w];
        }
    }
    if (t < 64) {
        const int c = t & 31, pw = (t < 32) ? 0 : 65;
        g_x[((size_t)b * NPIX + hp * PADW + pw) * CIN + cin0 + c] = zz;
    }
    __syncthreads();
    {
        const int c = t & 31, w0 = t >> 5;
        const float st = g_styles[b * CIN + cin0 + c];
        for (int w = w0; w < 64; w += 8) {
            g_x[((size_t)b * NPIX + hp * PADW + (w + 1)) * CIN + cin0 + c] =
                __float2half(tile[c][w] * st);
        }
    }
}

// ---------------------------------------------------------------------------
// main conv kernel: fp16 implicit GEMM, B-halo reuse, 64x64 warp tiles
// CTA: M=128 x N=128 pixels (2 rows), 128 threads / 4 warps, 2 CTAs/SM
// loop: 8 cin-chunks x 9 taps = 72 iters; A 16KB/iter, B halo 33.8KB/chunk
// ---------------------------------------------------------------------------
#define A_BUF   16384
#define OFF_B0  32768
#define B_BUF   33792                 // 264 rows x 128B
#define SMEM_DYN (OFF_B0 + 2 * B_BUF) // 100352

extern __shared__ __align__(1024) char smem[];

__global__ void __launch_bounds__(128, 2)
k_conv(const float* __restrict__ bias,
       const float* __restrict__ noise_const,
       const float* __restrict__ noise_strength,
       float* __restrict__ out) {
    const int tid   = threadIdx.x;           // 0..127
    const int wid   = tid >> 5;              // 0..3
    const int lid   = tid & 31;
    const int ptile = blockIdx.x;            // 0..31 (2 image rows each)
    const int cout0 = blockIdx.y * 128;      // 0..3
    const int b     = blockIdx.z;
    const int wm    = wid >> 1;              // 0..1 (M warp: 64 rows)
    const int wn    = wid & 1;               // 0..1 (N warp: 64 pixels)

    const uint32_t sb = smem_u32(smem);

    // ---- loader invariants
    const size_t arow = (size_t)(cout0 + tid) * CIN;
    const size_t pixbase = (size_t)b * NPIX + (size_t)ptile * 132;

    uint32_t swA[8];
#pragma unroll
    for (int sg = 0; sg < 8; sg++)
        swA[sg] = sw128((uint32_t)(tid * 128 + sg * 16));

    // ---- ldmatrix per-lane bases
    uint32_t aoff[4];
#pragma unroll
    for (int mt = 0; mt < 4; mt++)
        aoff[mt] = (uint32_t)((wm * 64 + mt * 16 + (lid & 15)) << 7) + ((lid >> 4) << 4);
    // B: 4 ldsm4 per kk, each covers 16 pixels (2 n-tiles)
    uint32_t q0b[4];
#pragma unroll
    for (int p = 0; p < 4; p++) {
        const int plocal = wn * 64 + p * 16 + ((lid >> 4) & 1) * 8 + (lid & 7);
        const int q0 = (plocal >> 6) * 66 + (plocal & 63);
        q0b[p] = (uint32_t)(q0 * 128) + (((lid >> 3) & 1) << 4);
    }

    float acc[4][8][4];
#pragma unroll
    for (int mt = 0; mt < 4; mt++)
#pragma unroll
        for (int nt = 0; nt < 8; nt++)
#pragma unroll
            for (int i = 0; i < 4; i++) acc[mt][nt][i] = 0.f;

    // ---- stage loader: A(it) always (128 rows / 128 thr); B halo when tap==0
    auto load_stage = [&](int it) {
        const int chunk = it / 9, tap = it - chunk * 9;
        const int cin0 = chunk << 6;
        {
            const char* asrc = (const char*)(g_a + ((size_t)tap * COUT * CIN + arow + cin0));
            const uint32_t da = sb + (uint32_t)(it & 1) * A_BUF;
#pragma unroll
            for (int sg = 0; sg < 8; sg++) cpa16(da + swA[sg], asrc + sg * 16);
        }
        if (tap == 0) {
            const uint32_t db = sb + OFF_B0 + (uint32_t)(chunk & 1) * B_BUF;
#pragma unroll
            for (int rep = 0; rep < 2; rep++) {
                const int hr = rep * 128 + tid;
                const char* bsrc = (const char*)(g_x + ((pixbase + hr) * CIN + cin0));
#pragma unroll
                for (int sg = 0; sg < 8; sg++)
                    cpa16(db + sw128((uint32_t)(hr * 128 + sg * 16)), bsrc + sg * 16);
            }
            if (tid < 8) {
                const int hr = 256 + tid;
                const char* bsrc = (const char*)(g_x + ((pixbase + hr) * CIN + cin0));
#pragma unroll
                for (int sg = 0; sg < 8; sg++)
                    cpa16(db + sw128((uint32_t)(hr * 128 + sg * 16)), bsrc + sg * 16);
            }
        }
        CP_COMMIT();
    };

    load_stage(0);

#pragma unroll 1
    for (int it = 0; it < 72; it++) {
        __syncthreads();                       // compute(it-1) done -> bufs free
        if (it + 1 < 72) { load_stage(it + 1); CP_WAIT1(); }
        else             { CP_WAIT0(); }
        __syncthreads();                       // A(it), B(chunk) visible

        const int chunk = it / 9, tap = it - chunk * 9;
        const uint32_t stgA = sb + (uint32_t)(it & 1) * A_BUF;
        const uint32_t bbase = sb + OFF_B0 + (uint32_t)(chunk & 1) * B_BUF;
        const uint32_t toff = (uint32_t)(((tap / 3) * 66 + (tap % 3)) * 128);

#pragma unroll
        for (int kk = 0; kk < 4; kk++) {
            uint32_t af[4][4], bf[4][4];
#pragma unroll
            for (int mt = 0; mt < 4; mt++)
                ldsm4(af[mt], stgA + sw128(aoff[mt] + kk * 32));
#pragma unroll
            for (int p = 0; p < 4; p++)
                ldsm4(bf[p], bbase + sw128(q0b[p] + toff + kk * 32));
#pragma unroll
            for (int p = 0; p < 4; p++)
#pragma unroll
                for (int h2 = 0; h2 < 2; h2++)
#pragma unroll
                    for (int mt = 0; mt < 4; mt++)
                        mma_f16(acc[mt][p * 2 + h2], af[mt], &bf[p][h2 * 2]);
        }
    }

    // ---- epilogue: demodulate, noise, bias, lrelu*sqrt(2), float2 stores
    const int g = lid >> 2, t2 = (lid & 3) * 2;
    const float ns = noise_strength[0];
    float nz[8][2];
    int hh[8], ww[8];
#pragma unroll
    for (int nt = 0; nt < 8; nt++) {
        const int n = ptile * 128 + wn * 64 + nt * 8 + t2;
        hh[nt] = n >> 6; ww[nt] = n & 63;
        nz[nt][0] = noise_const[hh[nt] * RES + ww[nt]] * ns;
        nz[nt][1] = noise_const[hh[nt] * RES + ww[nt] + 1] * ns;
    }
#pragma unroll
    for (int mt = 0; mt < 4; mt++) {
#pragma unroll
        for (int rr = 0; rr < 2; rr++) {
            const int co = cout0 + wm * 64 + mt * 16 + g + rr * 8;
            const float dc = g_dcoefs[b * COUT + co];
            const float bi = bias[co];
#pragma unroll
            for (int nt = 0; nt < 8; nt++) {
                float v0 = acc[mt][nt][rr * 2 + 0] * dc + nz[nt][0] + bi;
                float v1 = acc[mt][nt][rr * 2 + 1] * dc + nz[nt][1] + bi;
                v0 = (v0 > 0.f ? v0 : 0.2f * v0) * 1.4142135623730951f;
                v1 = (v1 > 0.f ? v1 : 0.2f * v1) * 1.4142135623730951f;
                float2* o = (float2*)&out[(((size_t)b * COUT + co) * RES + hh[nt]) * RES + ww[nt]];
                *o = make_float2(v0, v1);
            }
        }
    }
}

// ---------------------------------------------------------------------------
// launch: 4 kernels (ncu -s 5 lands on k_conv)
// ---------------------------------------------------------------------------
extern "C" void kernel_launch(void* const* d_in, const int* in_sizes, int n_in,
                              void* d_out, int out_size) {
    (void)in_sizes; (void)n_in; (void)out_size;
    const float* x              = (const float*)d_in[0];
    const float* w              = (const float*)d_in[1];
    const float* affine_w       = (const float*)d_in[2];
    const float* affine_b       = (const float*)d_in[3];
    const float* weight         = (const float*)d_in[4];
    const float* bias           = (const float*)d_in[5];
    const float* noise_const    = (const float*)d_in[6];
    const float* noise_strength = (const float*)d_in[7];
    float* out = (float*)d_out;

    cudaFuncSetAttribute(k_conv, cudaFuncAttributeMaxDynamicSharedMemorySize, SMEM_DYN);

    k_styles<<<192, 256>>>(w, affine_w, affine_b);
    k_prep<<<COUT, 512>>>(weight);
    k_pack_x<<<dim3(16, 66, BB), 256>>>(x);

    dim3 grid(32, COUT / 128, BB);
    k_conv<<<grid, 128, SMEM_DYN>>>(bias, noise_const, noise_strength, out);
}

// round 14
// speedup vs baseline: 1.6893x; 1.6893x over previous
#include <cuda_runtime.h>
#include <cuda_fp16.h>
#include <cstdint>

#define BB    16
#define CIN   512
#define COUT  512
#define RES   64
#define WDIM  512
#define PADW  66
#define NPIX  (PADW * PADW)

// ---------------------------------------------------------------------------
// device scratch (static globals — no allocations allowed)
// ---------------------------------------------------------------------------
__device__ float g_proj[BB * 3 * CIN];
__device__ float g_styles[BB * CIN];
__device__ float g_dcoefs[BB * COUT];
__device__ __align__(1024) __half g_a[9ull * COUT * CIN];          // [tap][cout][cin]
__device__ __align__(1024) __half g_x[(size_t)BB * NPIX * CIN];    // [b][pixel][cin]

// ---------------------------------------------------------------------------
// PTX helpers (baseline compute_103-safe)
// ---------------------------------------------------------------------------
__device__ __forceinline__ uint32_t smem_u32(const void* p) {
    uint32_t a;
    asm("{ .reg .u64 t; cvta.to.shared.u64 t, %1; cvt.u32.u64 %0, t; }" : "=r"(a) : "l"(p));
    return a;
}
__device__ __forceinline__ void cpa16(uint32_t dst, const void* src) {
    asm volatile("cp.async.cg.shared.global [%0], [%1], 16;" :: "r"(dst), "l"(src));
}
#define CP_COMMIT()  asm volatile("cp.async.commit_group;" ::: "memory")
#define CP_WAIT1()   asm volatile("cp.async.wait_group 1;" ::: "memory")
#define CP_WAIT0()   asm volatile("cp.async.wait_group 0;" ::: "memory")

__device__ __forceinline__ void ldsm4(uint32_t* r, uint32_t a) {
    asm volatile("ldmatrix.sync.aligned.m8n8.x4.shared.b16 {%0,%1,%2,%3}, [%4];"
        : "=r"(r[0]), "=r"(r[1]), "=r"(r[2]), "=r"(r[3]) : "r"(a));
}
__device__ __forceinline__ void mma_f16(float* c, const uint32_t* a, const uint32_t* b) {
    asm volatile("mma.sync.aligned.m16n8k16.row.col.f32.f16.f16.f32 "
        "{%0,%1,%2,%3}, {%4,%5,%6,%7}, {%8,%9}, {%0,%1,%2,%3};"
        : "+f"(c[0]), "+f"(c[1]), "+f"(c[2]), "+f"(c[3])
        : "r"(a[0]), "r"(a[1]), "r"(a[2]), "r"(a[3]), "r"(b[0]), "r"(b[1]));
}
__device__ __forceinline__ uint32_t sw128(uint32_t off) {
    return off ^ ((off >> 3) & 0x70);
}

// ---------------------------------------------------------------------------
// prep kernel 1: coalesced styles GEMV (warp per affine_w row)
// ---------------------------------------------------------------------------
__global__ void k_styles(const float* __restrict__ w,
                         const float* __restrict__ affine_w,
                         const float* __restrict__ affine_b) {
    __shared__ float sw[BB][WDIM];
    const int tid = threadIdx.x;
    for (int i = tid; i < BB * WDIM; i += 256)
        ((float*)sw)[i] = w[i];
    __syncthreads();

    const int wid = tid >> 5, lid = tid & 31;
    const int j = blockIdx.x * 8 + wid;
    const float* __restrict__ row = affine_w + (size_t)j * WDIM;

    float acc[BB];
#pragma unroll
    for (int b = 0; b < BB; b++) acc[b] = 0.f;
#pragma unroll 4
    for (int k = lid; k < WDIM; k += 32) {
        const float rv = row[k];
#pragma unroll
        for (int b = 0; b < BB; b++) acc[b] += rv * sw[b][k];
    }
#pragma unroll
    for (int b = 0; b < BB; b++)
#pragma unroll
        for (int off = 16; off > 0; off >>= 1)
            acc[b] += __shfl_xor_sync(0xFFFFFFFFu, acc[b], off);

    if (lid < BB) {
        const float gain = 1.0f / sqrtf((float)WDIM);
        g_proj[lid * 3 * CIN + j] = acc[lid] * gain + affine_b[j];
    }
}

// ---------------------------------------------------------------------------
// prep kernel 2 (fused): styles = m1*m2+m3, pack weights fp16, wsq, dcoefs
// ---------------------------------------------------------------------------
__global__ void k_prep(const float* __restrict__ weight) {
    const int co = blockIdx.x, ci = threadIdx.x;

    float st[BB];
#pragma unroll
    for (int b = 0; b < BB; b++) {
        const float m1 = g_proj[b * 3 * CIN + 0 * CIN + ci];
        const float m2 = g_proj[b * 3 * CIN + 1 * CIN + ci];
        const float m3 = g_proj[b * 3 * CIN + 2 * CIN + ci];
        st[b] = m1 * m2 + m3;
    }
    if (co == 0) {
#pragma unroll
        for (int b = 0; b < BB; b++) g_styles[b * CIN + ci] = st[b];
    }

    const float* __restrict__ wp = weight + ((size_t)co * CIN + ci) * 9;
    float s = 0.f;
#pragma unroll
    for (int t = 0; t < 9; t++) {
        const float v = wp[t];
        s += v * v;
        g_a[((size_t)t * COUT + co) * CIN + ci] = __float2half(v);
    }
    float p[BB];
#pragma unroll
    for (int b = 0; b < BB; b++) p[b] = st[b] * st[b] * s;
#pragma unroll
    for (int b = 0; b < BB; b++)
#pragma unroll
        for (int off = 16; off > 0; off >>= 1)
            p[b] += __shfl_xor_sync(0xFFFFFFFFu, p[b], off);
    __shared__ float red[BB][17];
    const int wrp = ci >> 5, lane = ci & 31;
    if (lane == 0)
#pragma unroll
        for (int b = 0; b < BB; b++) red[b][wrp] = p[b];
    __syncthreads();
    if (ci < BB) {
        float acc = 0.f;
#pragma unroll
        for (int k = 0; k < 16; k++) acc += red[ci][k];
        g_dcoefs[ci * COUT + co] = rsqrtf(acc + 1e-8f);
    }
}

// ---------------------------------------------------------------------------
// prep kernel 3: pack modulated input (fp16) + padding ring (fused)
// ---------------------------------------------------------------------------
__global__ void k_pack_x(const float* __restrict__ x) {
    const int b = blockIdx.z, hp = blockIdx.y, cin0 = blockIdx.x * 32;
    const int t = threadIdx.x;
    const __half zz = __float2half(0.f);

    if (hp == 0 || hp == 65) {
        for (int idx = t; idx < 66 * 32; idx += 256) {
            const int pw = idx >> 5, c = idx & 31;
            g_x[((size_t)b * NPIX + hp * PADW + pw) * CIN + cin0 + c] = zz;
        }
        return;
    }
    const int h = hp - 1;
    __shared__ float tile[32][65];
    {
        const int w = t & 63, i0 = t >> 6;
#pragma unroll
        for (int j = 0; j < 8; j++) {
            const int ci = i0 * 8 + j;
            tile[ci][w] = x[(((size_t)b * CIN + cin0 + ci) * RES + h) * RES + w];
        }
    }
    if (t < 64) {
        const int c = t & 31, pw = (t < 32) ? 0 : 65;
        g_x[((size_t)b * NPIX + hp * PADW + pw) * CIN + cin0 + c] = zz;
    }
    __syncthreads();
    {
        const int c = t & 31, w0 = t >> 5;
        const float st = g_styles[b * CIN + cin0 + c];
        for (int w = w0; w < 64; w += 8) {
            g_x[((size_t)b * NPIX + hp * PADW + (w + 1)) * CIN + cin0 + c] =
                __float2half(tile[c][w] * st);
        }
    }
}

// ---------------------------------------------------------------------------
// main conv kernel: fp16 implicit GEMM, B-halo reuse
// CTA: M=128 couts x N=256 pixels (4 rows), 512 thr / 16 warps (M4 x N4),
// warp tile 32x64, 1 CTA/SM. loop: 8 chunks x 9 taps = 72 iters.
// A 16KB/iter double-buffered; B halo 50.7KB/chunk double-buffered.
// ---------------------------------------------------------------------------
#define A_BUF   16384
#define OFF_B0  32768
#define B_BUF   50688                 // 396 rows x 128B
#define SMEM_DYN (OFF_B0 + 2 * B_BUF) // 134144

extern __shared__ __align__(1024) char smem[];

__global__ void __launch_bounds__(512, 1)
k_conv(const float* __restrict__ bias,
       const float* __restrict__ noise_const,
       const float* __restrict__ noise_strength,
       float* __restrict__ out) {
    const int tid   = threadIdx.x;           // 0..511
    const int wid   = tid >> 5;              // 0..15
    const int lid   = tid & 31;
    const int ptile = blockIdx.x;            // 0..15 (4 image rows each)
    const int cout0 = blockIdx.y * 128;      // 0..3
    const int b     = blockIdx.z;
    const int wm    = wid >> 2;              // 0..3 (M warp: 32 rows)
    const int wn    = wid & 3;               // 0..3 (N warp: 64 pixels)

    const uint32_t sb = smem_u32(smem);

    // ---- loader invariants
    const size_t arow = (size_t)(cout0 + (tid & 127)) * CIN;
    // halo: padded rows [4*ptile .. 4*ptile+5] x 66 cols = 396 rows
    const size_t pixbase = (size_t)b * NPIX + (size_t)ptile * 264;

    uint32_t swr[8];
#pragma unroll
    for (int sg = 0; sg < 8; sg++)
        swr[sg] = sw128((uint32_t)((tid & 127) * 128 + sg * 16));   // A rows
    uint32_t swb[8];
#pragma unroll
    for (int sg = 0; sg < 8; sg++)
        swb[sg] = sw128((uint32_t)(tid * 128 + sg * 16));           // B rows (tid<396)

    // ---- ldmatrix per-lane bases
    uint32_t aoff[2];
#pragma unroll
    for (int mt = 0; mt < 2; mt++)
        aoff[mt] = (uint32_t)((wm * 32 + mt * 16 + (lid & 15)) << 7) + ((lid >> 4) << 4);
    uint32_t q0b[4];
#pragma unroll
    for (int p = 0; p < 4; p++) {
        const int plocal = wn * 64 + p * 16 + ((lid >> 4) & 1) * 8 + (lid & 7);
        const int q0 = (plocal >> 6) * 66 + (plocal & 63);
        q0b[p] = (uint32_t)(q0 * 128) + (((lid >> 3) & 1) << 4);
    }

    float acc[2][8][4];
#pragma unroll
    for (int mt = 0; mt < 2; mt++)
#pragma unroll
        for (int nt = 0; nt < 8; nt++)
#pragma unroll
            for (int i = 0; i < 4; i++) acc[mt][nt][i] = 0.f;

    // ---- stage loader: A(it) by threads 0-127; B halo (396 rows) on tap==0
    auto load_stage = [&](int it) {
        const int chunk = it / 9, tap = it - chunk * 9;
        const int cin0 = chunk << 6;
        if (tid < 128) {
            const char* asrc = (const char*)(g_a + ((size_t)tap * COUT * CIN + arow + cin0));
            const uint32_t da = sb + (uint32_t)(it & 1) * A_BUF;
#pragma unroll
            for (int sg = 0; sg < 8; sg++) cpa16(da + swr[sg], asrc + sg * 16);
        }
        if (tap == 0 && tid < 396) {
            const uint32_t db = sb + OFF_B0 + (uint32_t)(chunk & 1) * B_BUF;
            const char* bsrc = (const char*)(g_x + ((pixbase + tid) * CIN + cin0));
#pragma unroll
            for (int sg = 0; sg < 8; sg++) cpa16(db + swb[sg], bsrc + sg * 16);
        }
        CP_COMMIT();
    };

    load_stage(0);

#pragma unroll 1
    for (int it = 0; it < 72; it++) {
        __syncthreads();                       // compute(it-1) done -> bufs free
        if (it + 1 < 72) { load_stage(it + 1); CP_WAIT1(); }
        else             { CP_WAIT0(); }
        __syncthreads();                       // A(it), B(chunk) visible

        const int chunk = it / 9, tap = it - chunk * 9;
        const uint32_t stgA = sb + (uint32_t)(it & 1) * A_BUF;
        const uint32_t bbase = sb + OFF_B0 + (uint32_t)(chunk & 1) * B_BUF;
        const uint32_t toff = (uint32_t)(((tap / 3) * 66 + (tap % 3)) * 128);

#pragma unroll
        for (int kk = 0; kk < 4; kk++) {
            uint32_t af[2][4], bf[4][4];
#pragma unroll
            for (int mt = 0; mt < 2; mt++)
                ldsm4(af[mt], stgA + sw128(aoff[mt] + kk * 32));
#pragma unroll
            for (int p = 0; p < 4; p++)
                ldsm4(bf[p], bbase + sw128(q0b[p] + toff + kk * 32));
#pragma unroll
            for (int p = 0; p < 4; p++)
#pragma unroll
                for (int h2 = 0; h2 < 2; h2++)
#pragma unroll
                    for (int mt = 0; mt < 2; mt++)
                        mma_f16(acc[mt][p * 2 + h2], af[mt], &bf[p][h2 * 2]);
        }
    }

    // ---- epilogue: demodulate, noise, bias, lrelu*sqrt(2), float2 stores
    const int g = lid >> 2, t2 = (lid & 3) * 2;
    const float ns = noise_strength[0];
    float nz[8][2];
    int hh[8], ww[8];
#pragma unroll
    for (int nt = 0; nt < 8; nt++) {
        const int n = ptile * 256 + wn * 64 + nt * 8 + t2;
        hh[nt] = n >> 6; ww[nt] = n & 63;
        nz[nt][0] = noise_const[hh[nt] * RES + ww[nt]] * ns;
        nz[nt][1] = noise_const[hh[nt] * RES + ww[nt] + 1] * ns;
    }
#pragma unroll
    for (int mt = 0; mt < 2; mt++) {
#pragma unroll
        for (int rr = 0; rr < 2; rr++) {
            const int co = cout0 + wm * 32 + mt * 16 + g + rr * 8;
            const float dc = g_dcoefs[b * COUT + co];
            const float bi = bias[co];
#pragma unroll
            for (int nt = 0; nt < 8; nt++) {
                float v0 = acc[mt][nt][rr * 2 + 0] * dc + nz[nt][0] + bi;
                float v1 = acc[mt][nt][rr * 2 + 1] * dc + nz[nt][1] + bi;
                v0 = (v0 > 0.f ? v0 : 0.2f * v0) * 1.4142135623730951f;
                v1 = (v1 > 0.f ? v1 : 0.2f * v1) * 1.4142135623730951f;
                float2* o = (float2*)&out[(((size_t)b * COUT + co) * RES + hh[nt]) * RES + ww[nt]];
                *o = make_float2(v0, v1);
            }
        }
    }
}

// ---------------------------------------------------------------------------
// launch: 4 kernels (ncu -s 5 lands on k_conv)
// ---------------------------------------------------------------------------
extern "C" void kernel_launch(void* const* d_in, const int* in_sizes, int n_in,
                              void* d_out, int out_size) {
    (void)in_sizes; (void)n_in; (void)out_size;
    const float* x              = (const float*)d_in[0];
    const float* w              = (const float*)d_in[1];
    const float* affine_w       = (const float*)d_in[2];
    const float* affine_b       = (const float*)d_in[3];
    const float* weight         = (const float*)d_in[4];
    const float* bias           = (const float*)d_in[5];
    const float* noise_const    = (const float*)d_in[6];
    const float* noise_strength = (const float*)d_in[7];
    float* out = (float*)d_out;

    cudaFuncSetAttribute(k_conv, cudaFuncAttributeMaxDynamicSharedMemorySize, SMEM_DYN);

    k_styles<<<192, 256>>>(w, affine_w, affine_b);
    k_prep<<<COUT, 512>>>(weight);
    k_pack_x<<<dim3(16, 66, BB), 256>>>(x);

    dim3 grid(16, COUT / 128, BB);
    k_conv<<<grid, 512, SMEM_DYN>>>(bias, noise_const, noise_strength, out);
}